// round 10
// baseline (speedup 1.0000x reference)
#include <cuda_runtime.h>
#include <cuda_bf16.h>
#include <math.h>
#include <stdint.h>

#define SS   512
#define BB   64
#define EE   512
#define HH   768
#define G4   3072      // 4*H
#define SB   (SS*BB)   // 32768
#define VV   32000
#define NBLK_FWD 96

// ---------------- scratch (static device globals; allocation-free launch) --------
__device__ float g_xf [SB * G4];
__device__ float g_xb [SB * G4];
__device__ float g_hsf[SB * HH];
__device__ float g_hsb[SB * HH];
__device__ float g_hTW[BB * G4];
__device__ uint16_t g_hid_hi[2][BB * HH];
__device__ uint16_t g_hid_lo[2][BB * HH];
__device__ uint16_t g_emb_hi[VV * EE];      // bf16 hi plane of embedding
__device__ uint16_t g_emb_lo[VV * EE];      // bf16 lo (residual) plane
__device__ uint16_t g_wt_hi[2][G4 * EE];    // Wi_f / Wi_b transposed n-major planes
__device__ uint16_t g_wt_lo[2][G4 * EE];
__device__ unsigned g_bar_count;
__device__ unsigned g_bar_gen;

// accurate transcendentals (libm; validated at rel_err 8.3e-8 in R4)
__device__ __forceinline__ float sigmoidf_(float x) { return 1.0f / (1.0f + expf(-x)); }

__device__ __forceinline__ uint32_t smem_u32(const void* p) {
    uint32_t a;
    asm("{ .reg .u64 t; cvta.to.shared.u64 t, %1; cvt.u32.u64 %0, t; }" : "=r"(a) : "l"(p));
    return a;
}
__device__ __forceinline__ uint32_t bpack(float e0, float e1) {
    uint32_t r;
    asm("cvt.rn.bf16x2.f32 %0, %1, %2;" : "=r"(r) : "f"(e1), "f"(e0));
    return r;
}
__device__ __forceinline__ uint16_t bf16rn(float x) {
    __nv_bfloat16 h = __float2bfloat16(x);
    return *(uint16_t*)&h;
}

#define LDSM_X4(r0, r1, r2, r3, addr)                                           \
    asm volatile("ldmatrix.sync.aligned.m8n8.x4.shared.b16 {%0,%1,%2,%3}, [%4];" \
                 : "=r"(r0), "=r"(r1), "=r"(r2), "=r"(r3) : "r"(addr))

__device__ __forceinline__ void mma_bf16(float (&d)[4], const uint32_t (&a)[4],
                                         uint32_t b0, uint32_t b1) {
    asm volatile("mma.sync.aligned.m16n8k16.row.col.f32.bf16.bf16.f32 "
                 "{%0,%1,%2,%3}, {%4,%5,%6,%7}, {%8,%9}, {%0,%1,%2,%3};"
                 : "+f"(d[0]), "+f"(d[1]), "+f"(d[2]), "+f"(d[3])
                 : "r"(a[0]), "r"(a[1]), "r"(a[2]), "r"(a[3]), "r"(b0), "r"(b1));
}

// ---------------- cp.async helpers ------------------------------------------------
__device__ __forceinline__ void cp16(uint32_t dst, const void* src) {
    asm volatile("cp.async.cg.shared.global [%0], [%1], 16;\n" :: "r"(dst), "l"(src));
}
#define CP_COMMIT() asm volatile("cp.async.commit_group;\n" ::: "memory")
#define CP_WAIT(n)  asm volatile("cp.async.wait_group %0;\n" :: "n"(n) : "memory")

// =================== pre-conversion kernels =======================================
__global__ void conv_emb(const float4* __restrict__ E,
                         uint2* __restrict__ hi, uint2* __restrict__ lo, int n4)
{
    int i = blockIdx.x * 256 + threadIdx.x;
    if (i >= n4) return;
    float4 v = E[i];
    uint32_t bx = __float_as_uint(v.x), by = __float_as_uint(v.y);
    uint32_t bz = __float_as_uint(v.z), bw = __float_as_uint(v.w);
    hi[i] = make_uint2(__byte_perm(bx, by, 0x7632), __byte_perm(bz, bw, 0x7632));
    float lx = v.x - __uint_as_float(bx & 0xFFFF0000u);
    float ly = v.y - __uint_as_float(by & 0xFFFF0000u);
    float lz = v.z - __uint_as_float(bz & 0xFFFF0000u);
    float lw = v.w - __uint_as_float(bw & 0xFFFF0000u);
    lo[i] = make_uint2(bpack(lx, ly), bpack(lz, lw));
}

// transpose W[512][3072] -> planes [3072][512]
__global__ void conv_wt(const float* __restrict__ W,
                        uint16_t* __restrict__ hi, uint16_t* __restrict__ lo)
{
    __shared__ float tile[32][33];
    int n0 = blockIdx.x * 32, k0 = blockIdx.y * 32;
    int tx = threadIdx.x, ty = threadIdx.y;   // (32, 8)
    #pragma unroll
    for (int j = 0; j < 4; j++)
        tile[ty + 8 * j][tx] = W[(size_t)(k0 + ty + 8 * j) * G4 + n0 + tx];
    __syncthreads();
    #pragma unroll
    for (int j = 0; j < 4; j++) {
        int n = ty + 8 * j;
        float v = tile[tx][n];                // = W[k0+tx][n0+n]
        uint32_t b = __float_as_uint(v);
        size_t o = (size_t)(n0 + n) * EE + k0 + tx;
        hi[o] = (uint16_t)(b >> 16);
        lo[o] = bf16rn(v - __uint_as_float(b & 0xFFFF0000u));
    }
}

// =================== bf16x3 mma.sync GEMM (pre-converted, cp.async staged) ========
// CTA 128x128, BK=32, 2-stage cp.async; planes: Ahi/Alo/Bhi/Blo, 128 rows x 80B.
#define TSTRIDE 80
#define PL_SZ  (128 * TSTRIDE)       // 10240
#define CH_SZ  (4 * PL_SZ)           // 40960
#define GEMM_SMEM (2 * CH_SZ + 512)  // 82432

__global__ void __launch_bounds__(256, 2) mma_gemm(
    const int* __restrict__ tokens,
    const uint16_t* __restrict__ Whi, const uint16_t* __restrict__ Wlo,
    const float* __restrict__ bias1, const float* __restrict__ bias2,
    float* __restrict__ C)
{
    extern __shared__ char sm[];
    const uint32_t sbase = smem_u32(sm);
    const int t  = threadIdx.x;
    const int n0 = blockIdx.x * 128;
    const int m0 = blockIdx.y * 128;
    float* bsum = (float*)(sm + 2 * CH_SZ);
    if (t < 128) bsum[t] = bias1 ? (bias1[n0 + t] + bias2[n0 + t]) : 0.f;

    // staging mapping: thread -> (row, 16B segment); 2 rows per thread per plane
    const int r0i = t >> 2, seg = t & 3;
    const int r1i = r0i + 64;
    const uint16_t* agh0 = g_emb_hi + (size_t)tokens[m0 + r0i] * EE + seg * 8;
    const uint16_t* agl0 = g_emb_lo + (size_t)tokens[m0 + r0i] * EE + seg * 8;
    const uint16_t* agh1 = g_emb_hi + (size_t)tokens[m0 + r1i] * EE + seg * 8;
    const uint16_t* agl1 = g_emb_lo + (size_t)tokens[m0 + r1i] * EE + seg * 8;
    const uint16_t* bgh0 = Whi + (size_t)(n0 + r0i) * EE + seg * 8;
    const uint16_t* bgl0 = Wlo + (size_t)(n0 + r0i) * EE + seg * 8;
    const uint16_t* bgh1 = Whi + (size_t)(n0 + r1i) * EE + seg * 8;
    const uint16_t* bgl1 = Wlo + (size_t)(n0 + r1i) * EE + seg * 8;
    const uint32_t so0 = (uint32_t)(r0i * TSTRIDE + seg * 16);
    const uint32_t so1 = (uint32_t)(r1i * TSTRIDE + seg * 16);

    // fragment mapping (identical to validated R4 layout)
    const int lane = t & 31, wid = t >> 5;
    const int mbase = (wid & 3) * 32, nbase = (wid >> 2) * 64;
    const int lt = lane >> 3, ll = lane & 7;
    const int dr = (lt & 1) * 8, dk = (lt >> 1) * 8;
    const int a_off = (mbase + dr + ll) * TSTRIDE + dk * 2;
    const int b_off = (nbase + dr + ll) * TSTRIDE + dk * 2;

    float acc[2][8][4];
    #pragma unroll
    for (int a = 0; a < 2; a++)
        #pragma unroll
        for (int b = 0; b < 8; b++)
            #pragma unroll
            for (int c = 0; c < 4; c++) acc[a][b][c] = 0.f;

    // issue chunk 0
    {
        const uint32_t st = sbase;
        cp16(st + so0,             agh0);  cp16(st + so1,             agh1);
        cp16(st + PL_SZ + so0,     agl0);  cp16(st + PL_SZ + so1,     agl1);
        cp16(st + 2*PL_SZ + so0,   bgh0);  cp16(st + 2*PL_SZ + so1,   bgh1);
        cp16(st + 3*PL_SZ + so0,   bgl0);  cp16(st + 3*PL_SZ + so1,   bgl1);
        CP_COMMIT();
    }

    #pragma unroll 1
    for (int ch = 0; ch < 16; ch++) {
        CP_WAIT(0);
        __syncthreads();
        if (ch < 15) {
            const int k0 = (ch + 1) * 32;
            const uint32_t st = sbase + ((ch + 1) & 1) * CH_SZ;
            cp16(st + so0,           agh0 + k0);  cp16(st + so1,           agh1 + k0);
            cp16(st + PL_SZ + so0,   agl0 + k0);  cp16(st + PL_SZ + so1,   agl1 + k0);
            cp16(st + 2*PL_SZ + so0, bgh0 + k0);  cp16(st + 2*PL_SZ + so1, bgh1 + k0);
            cp16(st + 3*PL_SZ + so0, bgl0 + k0);  cp16(st + 3*PL_SZ + so1, bgl1 + k0);
            CP_COMMIT();
        }
        const uint32_t bu  = sbase + (ch & 1) * CH_SZ;
        const uint32_t Ahi = bu, Alo = bu + PL_SZ, Bhi = bu + 2*PL_SZ, Blo = bu + 3*PL_SZ;
        #pragma unroll
        for (int ks = 0; ks < 2; ks++) {
            uint32_t ah[2][4], al[2][4];
            #pragma unroll
            for (int mf = 0; mf < 2; mf++) {
                LDSM_X4(ah[mf][0], ah[mf][1], ah[mf][2], ah[mf][3],
                        Ahi + a_off + mf * 1280 + ks * 32);
                LDSM_X4(al[mf][0], al[mf][1], al[mf][2], al[mf][3],
                        Alo + a_off + mf * 1280 + ks * 32);
            }
            #pragma unroll
            for (int j = 0; j < 4; j++) {
                uint32_t bh[4], bl[4];
                LDSM_X4(bh[0], bh[1], bh[2], bh[3], Bhi + b_off + j * 1280 + ks * 32);
                LDSM_X4(bl[0], bl[1], bl[2], bl[3], Blo + b_off + j * 1280 + ks * 32);
                #pragma unroll
                for (int mf = 0; mf < 2; mf++) {
                    mma_bf16(acc[mf][2*j],   ah[mf], bh[0], bh[2]);
                    mma_bf16(acc[mf][2*j],   ah[mf], bl[0], bl[2]);
                    mma_bf16(acc[mf][2*j],   al[mf], bh[0], bh[2]);
                    mma_bf16(acc[mf][2*j+1], ah[mf], bh[1], bh[3]);
                    mma_bf16(acc[mf][2*j+1], ah[mf], bl[1], bl[3]);
                    mma_bf16(acc[mf][2*j+1], al[mf], bh[1], bh[3]);
                }
            }
        }
    }

    const int g = lane >> 2, tg = (lane & 3) * 2;
    #pragma unroll
    for (int mf = 0; mf < 2; mf++) {
        #pragma unroll
        for (int jj = 0; jj < 8; jj++) {
            const int nloc = nbase + jj * 8 + tg;
            const float b0 = bsum[nloc], b1 = bsum[nloc + 1];
            const int r0 = m0 + mbase + mf * 16 + g;
            const size_t col = (size_t)(n0 + nloc);
            *(float2*)(C + (size_t)r0 * G4 + col) =
                make_float2(acc[mf][jj][0] + b0, acc[mf][jj][1] + b1);
            *(float2*)(C + (size_t)(r0 + 8) * G4 + col) =
                make_float2(acc[mf][jj][2] + b0, acc[mf][jj][3] + b1);
        }
    }
}

// ---------------- software grid barrier -------------------------------------------
__device__ __forceinline__ void grid_bar(unsigned nblocks) {
    __threadfence();
    __syncthreads();
    if (threadIdx.x == 0) {
        unsigned gen = *(volatile unsigned*)&g_bar_gen;
        if (atomicAdd(&g_bar_count, 1u) == nblocks - 1u) {
            atomicExch(&g_bar_count, 0u);
            __threadfence();
            *(volatile unsigned*)&g_bar_gen = gen + 1u;
        } else {
            while (*(volatile unsigned*)&g_bar_gen == gen) { __nanosleep(64); }
        }
        __threadfence();
    }
    __syncthreads();
}

// ---------------- small fp32 GEMM (hTW only) --------------------------------------
__global__ void sgemm64(const float* __restrict__ A, const int* __restrict__ gather,
                        const float* __restrict__ W, int M, int N, int K,
                        const float* __restrict__ bias1, const float* __restrict__ bias2,
                        float* __restrict__ C)
{
    __shared__ __align__(16) float As[16][68];
    __shared__ __align__(16) float Bs[16][64];
    const int t  = threadIdx.x;
    const int m0 = blockIdx.y * 64;
    const int n0 = blockIdx.x * 64;
    const int c0 = 4 * (t & 15);
    const int r0 = 4 * (t >> 4);
    const int mload = t >> 2;
    const int kq    = (t & 3) * 4;
    const int nload = t & 63;
    const int kload = t >> 6;

    const float* arow;
    {
        int mg = m0 + mload;
        arow = gather ? (A + (size_t)gather[mg] * K) : (A + (size_t)mg * K);
    }

    float acc[4][4] = {};
    for (int k0 = 0; k0 < K; k0 += 16) {
        float4 a4 = *(const float4*)(arow + k0 + kq);
        As[kq + 0][mload] = a4.x; As[kq + 1][mload] = a4.y;
        As[kq + 2][mload] = a4.z; As[kq + 3][mload] = a4.w;
        #pragma unroll
        for (int p = 0; p < 4; p++) {
            int kk = kload + p * 4;
            Bs[kk][nload] = W[(size_t)(k0 + kk) * N + n0 + nload];
        }
        __syncthreads();
        #pragma unroll
        for (int kk = 0; kk < 16; kk++) {
            float4 a = *(const float4*)&As[kk][r0];
            float4 b = *(const float4*)&Bs[kk][c0];
            acc[0][0] += a.x*b.x; acc[0][1] += a.x*b.y; acc[0][2] += a.x*b.z; acc[0][3] += a.x*b.w;
            acc[1][0] += a.y*b.x; acc[1][1] += a.y*b.y; acc[1][2] += a.y*b.z; acc[1][3] += a.y*b.w;
            acc[2][0] += a.z*b.x; acc[2][1] += a.z*b.y; acc[2][2] += a.z*b.z; acc[2][3] += a.z*b.w;
            acc[3][0] += a.w*b.x; acc[3][1] += a.w*b.y; acc[3][2] += a.w*b.z; acc[3][3] += a.w*b.w;
        }
        __syncthreads();
    }
    float badd[4];
    #pragma unroll
    for (int j = 0; j < 4; j++) {
        float b = 0.f;
        if (bias1) b += bias1[n0 + c0 + j];
        if (bias2) b += bias2[n0 + c0 + j];
        badd[j] = b;
    }
    #pragma unroll
    for (int i = 0; i < 4; i++) {
        float4 v = make_float4(acc[i][0] + badd[0], acc[i][1] + badd[1],
                               acc[i][2] + badd[2], acc[i][3] + badd[3]);
        *(float4*)&C[(size_t)(m0 + r0 + i) * N + n0 + c0] = v;
    }
}

// ---------------- persistent forward LSTM scan (tensor-core, cp.async staged) ----
#define WSTRIDE 1552
#define HSTRIDE 144
#define HPL     9216                 // 64 rows x 144
#define HST_SZ  (2 * HPL)            // hi + lo per stage = 18432
#define FW_WH_HI 0
#define FW_WH_LO 49664
#define FW_HID   99328               // 3 stages x 18432 = 55296
#define FW_GS    154624              // 32 cols x 68 fp32 = 8704
#define FW_SMEM  163328

__global__ void __launch_bounds__(256, 1) fwd_lstm_mma(
    const float* __restrict__ Wh,    // [768][3072]
    const float* __restrict__ xf,    // [S*B][3072]
    float* __restrict__ hsf)         // [S*B][768]
{
    extern __shared__ char sm[];
    const uint32_t sbase = smem_u32(sm);
    float* gs = (float*)(sm + FW_GS);
    const int t  = threadIdx.x;
    const int j0 = blockIdx.x * 8;

    // stage Wh slice as bf16 hi/lo, n-major [32][768]
    for (int idx = t; idx < 768 * 32; idx += 256) {
        int n = idx & 31, k = idx >> 5;
        float v = Wh[(size_t)k * 3072 + (n >> 3) * 768 + j0 + (n & 7)];
        uint32_t b = __float_as_uint(v);
        *(uint16_t*)(sm + FW_WH_HI + n * WSTRIDE + k * 2) = (uint16_t)(b >> 16);
        *(uint16_t*)(sm + FW_WH_LO + n * WSTRIDE + k * 2) =
            bf16rn(v - __uint_as_float(b & 0xFFFF0000u));
    }

    const int lane = t & 31, wid = t >> 5;
    const int wm = wid & 3, wn = wid >> 2;
    const int lt = lane >> 3, ll = lane & 7;
    const int dr = (lt & 1) * 8, dk16 = (lt >> 1) * 16;
    const uint32_t a_off = (uint32_t)((wm * 16 + dr + ll) * HSTRIDE + dk16);
    const uint32_t b_hiA = sbase + FW_WH_HI + (wn * 16 + dr + ll) * WSTRIDE + dk16;
    const uint32_t b_loA = sbase + FW_WH_LO + (wn * 16 + dr + ll) * WSTRIDE + dk16;

    // hid staging map: 2 x 16B per plane per thread (full 128B rows)
    const int srow = t >> 2, sseg = t & 3;
    const uint32_t s_off = (uint32_t)(srow * HSTRIDE + sseg * 16);
    const int g_off = srow * 768 + sseg * 8;   // + ch*64, elements; second seg +32

    // epilogue mapping
    const int h_a = t & 7, row_a = t >> 3;
    const int h_b = h_a,   row_b = 32 + (t >> 3);
    float creg_a = 0.f, creg_b = 0.f;
    __syncthreads();

    for (int s = 0; s < SS; s++) {
        float xfa[4], xfb[4];
        {
            size_t ba = ((size_t)s * 64 + row_a) * 3072 + j0 + h_a;
            size_t bb = ((size_t)s * 64 + row_b) * 3072 + j0 + h_b;
            #pragma unroll
            for (int g = 0; g < 4; g++) { xfa[g] = xf[ba + g * 768]; xfb[g] = xf[bb + g * 768]; }
        }
        float acc[2][4] = {};
        if (s > 0) {
            const uint16_t* chi = g_hid_hi[s & 1];
            const uint16_t* clo = g_hid_lo[s & 1];
            // prologue: stage chunks 0, 1 (FULL rows: 2 segments per plane)
            #pragma unroll
            for (int p = 0; p < 2; p++) {
                const uint32_t st = sbase + FW_HID + p * HST_SZ;
                const int go = g_off + p * 64;
                cp16(st + s_off,            chi + go);
                cp16(st + s_off + 64,       chi + go + 32);
                cp16(st + HPL + s_off,      clo + go);
                cp16(st + HPL + s_off + 64, clo + go + 32);
                CP_COMMIT();
            }
            #pragma unroll 1
            for (int ch = 0; ch < 12; ch++) {
                if (ch < 11) { CP_WAIT(1); } else { CP_WAIT(0); }
                __syncthreads();
                if (ch < 10) {
                    const int nc = ch + 2;
                    const uint32_t st = sbase + FW_HID + (nc % 3) * HST_SZ;
                    const int go = g_off + nc * 64;
                    cp16(st + s_off,            chi + go);
                    cp16(st + s_off + 64,       chi + go + 32);
                    cp16(st + HPL + s_off,      clo + go);
                    cp16(st + HPL + s_off + 64, clo + go + 32);
                    CP_COMMIT();
                }
                const uint32_t Ah  = sbase + FW_HID + (ch % 3) * HST_SZ + a_off;
                const uint32_t Al  = Ah + HPL;
                const uint32_t wko = (uint32_t)ch * 128;
                #pragma unroll
                for (int kf = 0; kf < 4; kf++) {
                    uint32_t ah[4], al[4], bh[4], bl[4];
                    LDSM_X4(ah[0], ah[1], ah[2], ah[3], Ah + kf * 32);
                    LDSM_X4(al[0], al[1], al[2], al[3], Al + kf * 32);
                    LDSM_X4(bh[0], bh[1], bh[2], bh[3], b_hiA + wko + kf * 32);
                    LDSM_X4(bl[0], bl[1], bl[2], bl[3], b_loA + wko + kf * 32);
                    mma_bf16(acc[0], ah, bh[0], bh[2]);
                    mma_bf16(acc[0], ah, bl[0], bl[2]);
                    mma_bf16(acc[0], al, bh[0], bh[2]);
                    mma_bf16(acc[1], ah, bh[1], bh[3]);
                    mma_bf16(acc[1], ah, bl[1], bl[3]);
                    mma_bf16(acc[1], al, bh[1], bh[3]);
                }
            }
        }
        // stash gates
        {
            const int g = lane >> 2, tg = (lane & 3) * 2;
            #pragma unroll
            for (int nf = 0; nf < 2; nf++) {
                int col = wn * 16 + nf * 8 + tg;
                int row = wm * 16 + g;
                gs[col * 68 + row]           = acc[nf][0];
                gs[(col + 1) * 68 + row]     = acc[nf][1];
                gs[col * 68 + row + 8]       = acc[nf][2];
                gs[(col + 1) * 68 + row + 8] = acc[nf][3];
            }
        }
        __syncthreads();

        uint16_t* nhi = g_hid_hi[(s + 1) & 1];
        uint16_t* nlo = g_hid_lo[(s + 1) & 1];
        {
            float gr = gs[( 0 + h_a) * 68 + row_a] + xfa[0];
            float gf = gs[( 8 + h_a) * 68 + row_a] + xfa[1];
            float gg = gs[(16 + h_a) * 68 + row_a] + xfa[2];
            float go = gs[(24 + h_a) * 68 + row_a] + xfa[3];
            float c  = sigmoidf_(gf) * creg_a + sigmoidf_(gr) * tanhf(gg);
            creg_a = c;
            float hv = sigmoidf_(go) * tanhf(c);
            int gi = row_a * 768 + j0 + h_a;
            uint32_t b = __float_as_uint(hv);
            nhi[gi] = (uint16_t)(b >> 16);
            nlo[gi] = bf16rn(hv - __uint_as_float(b & 0xFFFF0000u));
            hsf[((size_t)s * 64 + row_a) * 768 + j0 + h_a] = hv;
        }
        {
            float gr = gs[( 0 + h_b) * 68 + row_b] + xfb[0];
            float gf = gs[( 8 + h_b) * 68 + row_b] + xfb[1];
            float gg = gs[(16 + h_b) * 68 + row_b] + xfb[2];
            float go = gs[(24 + h_b) * 68 + row_b] + xfb[3];
            float c  = sigmoidf_(gf) * creg_b + sigmoidf_(gr) * tanhf(gg);
            creg_b = c;
            float hv = sigmoidf_(go) * tanhf(c);
            int gi = row_b * 768 + j0 + h_b;
            uint32_t b = __float_as_uint(hv);
            nhi[gi] = (uint16_t)(b >> 16);
            nlo[gi] = bf16rn(hv - __uint_as_float(b & 0xFFFF0000u));
            hsf[((size_t)s * 64 + row_b) * 768 + j0 + h_b] = hv;
        }
        grid_bar(gridDim.x);
    }
}

// ---------------- backward direction (pipelined loads) ----------------------------
__global__ void bwd_scan(const float* __restrict__ xb, const float* __restrict__ hTW,
                         float* __restrict__ hsb)
{
    int tid = blockIdx.x * blockDim.x + threadIdx.x;
    int h = tid % 768, b = tid / 768;
    float hr = hTW[b * 3072 + h];
    float hf = hTW[b * 3072 + 768 + h];
    float hg = hTW[b * 3072 + 1536 + h];
    float ho = hTW[b * 3072 + 2304 + h];
    size_t base = ((size_t)511 * 64 + b) * 3072 + h;
    float a0 = xb[base], a1 = xb[base + 768], a2 = xb[base + 1536], a3 = xb[base + 2304];
    float c2 = 0.f;
    for (int s = SS - 1; s >= 0; s--) {
        float x0 = a0, x1 = a1, x2 = a2, x3 = a3;
        if (s > 0) {
            base -= (size_t)64 * 3072;
            a0 = xb[base]; a1 = xb[base + 768]; a2 = xb[base + 1536]; a3 = xb[base + 2304];
        }
        float r = sigmoidf_(x0 + hr), f = sigmoidf_(x1 + hf);
        float g = tanhf(x2 + hg),     o = sigmoidf_(x3 + ho);
        c2 = f * c2 + r * g;
        hsb[((size_t)s * 64 + b) * 768 + h] = o * tanhf(c2);
    }
}

// ---------------- output GEMM -----------------------------------------------------
__global__ void out_gemm(const float* __restrict__ hsf, const float* __restrict__ hsb,
                         const float* __restrict__ Wout, const float* __restrict__ bout,
                         const int* __restrict__ tokens, float* __restrict__ out)
{
    __shared__ __align__(16) float As[16][132];
    __shared__ __align__(16) float Bs[16][32];
    const int t  = threadIdx.x;
    const int m0 = blockIdx.y * 128;
    const int c0 = 4 * (t & 7);
    const int r0 = 4 * (t >> 3);
    const int mload = t >> 2;
    const int kq    = (t & 3) * 4;
    float acc[4][4] = {};
    for (int k0 = 0; k0 < 1536; k0 += 16) {
        const float* srcbase = (k0 < 768) ? hsf : hsb;
        int koff = (k0 < 768) ? k0 : (k0 - 768);
        #pragma unroll
        for (int half = 0; half < 2; half++) {
            int m = mload + half * 64;
            float4 v = *(const float4*)(srcbase + (size_t)(m0 + m) * 768 + koff + kq);
            As[kq + 0][m] = v.x; As[kq + 1][m] = v.y;
            As[kq + 2][m] = v.z; As[kq + 3][m] = v.w;
        }
        #pragma unroll
        for (int p = 0; p < 2; p++) {
            int idx = t + p * 256;
            int kk = idx >> 5, n = idx & 31;
            Bs[kk][n] = Wout[(size_t)(k0 + kk) * 32 + n];
        }
        __syncthreads();
        #pragma unroll
        for (int kk = 0; kk < 16; kk++) {
            float4 a = *(const float4*)&As[kk][r0];
            float4 b = *(const float4*)&Bs[kk][c0];
            acc[0][0] += a.x*b.x; acc[0][1] += a.x*b.y; acc[0][2] += a.x*b.z; acc[0][3] += a.x*b.w;
            acc[1][0] += a.y*b.x; acc[1][1] += a.y*b.y; acc[1][2] += a.y*b.z; acc[1][3] += a.y*b.w;
            acc[2][0] += a.z*b.x; acc[2][1] += a.z*b.y; acc[2][2] += a.z*b.z; acc[2][3] += a.z*b.w;
            acc[3][0] += a.w*b.x; acc[3][1] += a.w*b.y; acc[3][2] += a.w*b.z; acc[3][3] += a.w*b.w;
        }
        __syncthreads();
    }
    #pragma unroll
    for (int i = 0; i < 4; i++) {
        int m = m0 + r0 + i;
        float4 v = make_float4(acc[i][0] + bout[c0],     acc[i][1] + bout[c0 + 1],
                               acc[i][2] + bout[c0 + 2], acc[i][3] + bout[c0 + 3]);
        if (c0 == 0 && tokens[m] == 1) v.x += 10000.0f;
        *(float4*)&out[(size_t)m * 32 + c0] = v;
    }
}

// ---------------- launch ----------------------------------------------------------
extern "C" void kernel_launch(void* const* d_in, const int* in_sizes, int n_in,
                              void* d_out, int out_size)
{
    const int*   tokens    = (const int*)  d_in[0];
    const float* embedding = (const float*)d_in[2];
    const float* Wi_f      = (const float*)d_in[3];
    const float* bi_f      = (const float*)d_in[4];
    const float* Wh_f      = (const float*)d_in[5];
    const float* bh_f      = (const float*)d_in[6];
    const float* Wi_b      = (const float*)d_in[7];
    const float* bi_b      = (const float*)d_in[8];
    const float* Wh_b      = (const float*)d_in[9];
    const float* bh_b      = (const float*)d_in[10];
    const float* Wout      = (const float*)d_in[11];
    const float* bout      = (const float*)d_in[12];
    float* out = (float*)d_out;

    float *xf, *xb, *hsf, *hsb, *hTW;
    uint16_t *ehi, *elo, *wthi, *wtlo;
    cudaGetSymbolAddress((void**)&xf,  g_xf);
    cudaGetSymbolAddress((void**)&xb,  g_xb);
    cudaGetSymbolAddress((void**)&hsf, g_hsf);
    cudaGetSymbolAddress((void**)&hsb, g_hsb);
    cudaGetSymbolAddress((void**)&hTW, g_hTW);
    cudaGetSymbolAddress((void**)&ehi, g_emb_hi);
    cudaGetSymbolAddress((void**)&elo, g_emb_lo);
    cudaGetSymbolAddress((void**)&wthi, g_wt_hi);
    cudaGetSymbolAddress((void**)&wtlo, g_wt_lo);

    cudaFuncSetAttribute(fwd_lstm_mma, cudaFuncAttributeMaxDynamicSharedMemorySize, FW_SMEM);
    cudaFuncSetAttribute(mma_gemm, cudaFuncAttributeMaxDynamicSharedMemorySize, GEMM_SMEM);

    // 0: pre-convert embedding + Wi matrices to bf16 hi/lo planes
    conv_emb<<<(VV * EE / 4 + 255) / 256, 256>>>((const float4*)embedding,
                                                 (uint2*)ehi, (uint2*)elo, VV * EE / 4);
    conv_wt<<<dim3(G4 / 32, EE / 32), dim3(32, 8)>>>(Wi_f, wthi,            wtlo);
    conv_wt<<<dim3(G4 / 32, EE / 32), dim3(32, 8)>>>(Wi_b, wthi + G4 * EE,  wtlo + G4 * EE);

    // 1+2: input gate precompute on tensor cores (bf16x3, cp.async staged)
    dim3 gG(G4 / 128, SB / 128);
    mma_gemm<<<gG, 256, GEMM_SMEM>>>(tokens, wthi,           wtlo,           bi_f, bh_f, xf);
    mma_gemm<<<gG, 256, GEMM_SMEM>>>(tokens, wthi + G4 * EE, wtlo + G4 * EE, nullptr, nullptr, xb);

    // 3: forward recurrence (persistent, tensor-core)
    fwd_lstm_mma<<<NBLK_FWD, 256, FW_SMEM>>>(Wh_f, xf, hsf);

    // 4: hTW = hT @ Wh_b + bi_b + bh_b
    sgemm64<<<dim3(G4 / 64, 1), 256>>>(hsf + (size_t)(SS - 1) * BB * HH, nullptr, Wh_b,
                                       BB, G4, HH, bi_b, bh_b, hTW);

    // 5: backward direction
    bwd_scan<<<(BB * HH) / 256, 256>>>(xb, hTW, hsb);

    // 6: output projection + pad bias
    out_gemm<<<dim3(1, SB / 128), 256>>>(hsf, hsb, Wout, bout, tokens, out);
}

// round 12
// speedup vs baseline: 1.0515x; 1.0515x over previous
#include <cuda_runtime.h>
#include <cuda_bf16.h>
#include <math.h>
#include <stdint.h>

#define SS   512
#define BB   64
#define EE   512
#define HH   768
#define G4   3072      // 4*H
#define SB   (SS*BB)   // 32768
#define VV   32000
#define NBLK_FWD 96

// ---------------- scratch (static device globals; allocation-free launch) --------
__device__ float g_xf [SB * G4];
__device__ float g_xb [SB * G4];
__device__ float g_hsf[SB * HH];
__device__ float g_hsb[SB * HH];
__device__ float g_hTW[BB * G4];
__device__ uint16_t g_hid_hi[2][BB * HH];
__device__ uint16_t g_hid_lo[2][BB * HH];
__device__ uint16_t g_emb_hi[VV * EE];      // bf16 hi plane of embedding
__device__ uint16_t g_emb_lo[VV * EE];      // bf16 lo (residual) plane
__device__ uint16_t g_wt_hi[2][G4 * EE];    // Wi_f / Wi_b transposed n-major planes
__device__ uint16_t g_wt_lo[2][G4 * EE];
// two-level barrier state
__device__ unsigned g_cnt_sub[6 * 32];      // one counter per 128B line
__device__ unsigned g_cnt_top;
__device__ volatile unsigned g_gen2;

// accurate transcendentals (libm; validated at rel_err 8.3e-8 in R4)
__device__ __forceinline__ float sigmoidf_(float x) { return 1.0f / (1.0f + expf(-x)); }

__device__ __forceinline__ uint32_t smem_u32(const void* p) {
    uint32_t a;
    asm("{ .reg .u64 t; cvta.to.shared.u64 t, %1; cvt.u32.u64 %0, t; }" : "=r"(a) : "l"(p));
    return a;
}
__device__ __forceinline__ uint32_t bpack(float e0, float e1) {
    uint32_t r;
    asm("cvt.rn.bf16x2.f32 %0, %1, %2;" : "=r"(r) : "f"(e1), "f"(e0));
    return r;
}
__device__ __forceinline__ uint16_t bf16rn(float x) {
    __nv_bfloat16 h = __float2bfloat16(x);
    return *(uint16_t*)&h;
}

#define LDSM_X4(r0, r1, r2, r3, addr)                                           \
    asm volatile("ldmatrix.sync.aligned.m8n8.x4.shared.b16 {%0,%1,%2,%3}, [%4];" \
                 : "=r"(r0), "=r"(r1), "=r"(r2), "=r"(r3) : "r"(addr))

__device__ __forceinline__ void mma_bf16(float (&d)[4], const uint32_t (&a)[4],
                                         uint32_t b0, uint32_t b1) {
    asm volatile("mma.sync.aligned.m16n8k16.row.col.f32.bf16.bf16.f32 "
                 "{%0,%1,%2,%3}, {%4,%5,%6,%7}, {%8,%9}, {%0,%1,%2,%3};"
                 : "+f"(d[0]), "+f"(d[1]), "+f"(d[2]), "+f"(d[3])
                 : "r"(a[0]), "r"(a[1]), "r"(a[2]), "r"(a[3]), "r"(b0), "r"(b1));
}

// ---------------- cp.async helpers ------------------------------------------------
__device__ __forceinline__ void cp16(uint32_t dst, const void* src) {
    asm volatile("cp.async.cg.shared.global [%0], [%1], 16;\n" :: "r"(dst), "l"(src));
}
#define CP_COMMIT() asm volatile("cp.async.commit_group;\n" ::: "memory")
#define CP_WAIT(n)  asm volatile("cp.async.wait_group %0;\n" :: "n"(n) : "memory")

// ---------------- split two-level grid barrier ------------------------------------
__device__ __forceinline__ void bar_arrive(int bx) {
    __syncthreads();
    __threadfence();
    if (threadIdx.x == 0) {
        int grp = bx >> 4;                      // 6 groups of 16
        if (atomicAdd(&g_cnt_sub[grp * 32], 1u) == 15u) {
            if (atomicAdd(&g_cnt_top, 1u) == 5u) {
                #pragma unroll
                for (int i = 0; i < 6; i++) g_cnt_sub[i * 32] = 0u;
                g_cnt_top = 0u;
                __threadfence();
                g_gen2 = g_gen2 + 1u;
            }
        }
    }
}
__device__ __forceinline__ void bar_wait(unsigned target) {
    if (threadIdx.x == 0) {
        while (g_gen2 < target) { }
    }
    __syncthreads();
    __threadfence();
}

// =================== pre-conversion kernels =======================================
__global__ void conv_emb(const float4* __restrict__ E,
                         uint2* __restrict__ hi, uint2* __restrict__ lo, int n4)
{
    int i = blockIdx.x * 256 + threadIdx.x;
    if (i >= n4) return;
    float4 v = E[i];
    uint32_t bx = __float_as_uint(v.x), by = __float_as_uint(v.y);
    uint32_t bz = __float_as_uint(v.z), bw = __float_as_uint(v.w);
    hi[i] = make_uint2(__byte_perm(bx, by, 0x7632), __byte_perm(bz, bw, 0x7632));
    float lx = v.x - __uint_as_float(bx & 0xFFFF0000u);
    float ly = v.y - __uint_as_float(by & 0xFFFF0000u);
    float lz = v.z - __uint_as_float(bz & 0xFFFF0000u);
    float lw = v.w - __uint_as_float(bw & 0xFFFF0000u);
    lo[i] = make_uint2(bpack(lx, ly), bpack(lz, lw));
}

// transpose W[512][3072] -> planes [3072][512]
__global__ void conv_wt(const float* __restrict__ W,
                        uint16_t* __restrict__ hi, uint16_t* __restrict__ lo)
{
    __shared__ float tile[32][33];
    int n0 = blockIdx.x * 32, k0 = blockIdx.y * 32;
    int tx = threadIdx.x, ty = threadIdx.y;   // (32, 8)
    #pragma unroll
    for (int j = 0; j < 4; j++)
        tile[ty + 8 * j][tx] = W[(size_t)(k0 + ty + 8 * j) * G4 + n0 + tx];
    __syncthreads();
    #pragma unroll
    for (int j = 0; j < 4; j++) {
        int n = ty + 8 * j;
        float v = tile[tx][n];                // = W[k0+tx][n0+n]
        uint32_t b = __float_as_uint(v);
        size_t o = (size_t)(n0 + n) * EE + k0 + tx;
        hi[o] = (uint16_t)(b >> 16);
        lo[o] = bf16rn(v - __uint_as_float(b & 0xFFFF0000u));
    }
}

// =================== bf16x3 mma.sync GEMM (pre-converted, cp.async staged) ========
// CTA 128x128, BK=32, 2-stage cp.async; planes: Ahi/Alo/Bhi/Blo, 128 rows x 80B.
#define TSTRIDE 80
#define PL_SZ  (128 * TSTRIDE)       // 10240
#define CH_SZ  (4 * PL_SZ)           // 40960
#define GEMM_SMEM (2 * CH_SZ + 512)  // 82432

__global__ void __launch_bounds__(256, 2) mma_gemm(
    const int* __restrict__ tokens,
    const uint16_t* __restrict__ Whi, const uint16_t* __restrict__ Wlo,
    const float* __restrict__ bias1, const float* __restrict__ bias2,
    float* __restrict__ C)
{
    extern __shared__ char sm[];
    const uint32_t sbase = smem_u32(sm);
    const int t  = threadIdx.x;
    const int n0 = blockIdx.x * 128;
    const int m0 = blockIdx.y * 128;
    float* bsum = (float*)(sm + 2 * CH_SZ);
    if (t < 128) bsum[t] = bias1 ? (bias1[n0 + t] + bias2[n0 + t]) : 0.f;

    // staging mapping: thread -> (row, 16B segment); 2 rows per thread per plane
    const int r0i = t >> 2, seg = t & 3;
    const int r1i = r0i + 64;
    const uint16_t* agh0 = g_emb_hi + (size_t)tokens[m0 + r0i] * EE + seg * 8;
    const uint16_t* agl0 = g_emb_lo + (size_t)tokens[m0 + r0i] * EE + seg * 8;
    const uint16_t* agh1 = g_emb_hi + (size_t)tokens[m0 + r1i] * EE + seg * 8;
    const uint16_t* agl1 = g_emb_lo + (size_t)tokens[m0 + r1i] * EE + seg * 8;
    const uint16_t* bgh0 = Whi + (size_t)(n0 + r0i) * EE + seg * 8;
    const uint16_t* bgl0 = Wlo + (size_t)(n0 + r0i) * EE + seg * 8;
    const uint16_t* bgh1 = Whi + (size_t)(n0 + r1i) * EE + seg * 8;
    const uint16_t* bgl1 = Wlo + (size_t)(n0 + r1i) * EE + seg * 8;
    const uint32_t so0 = (uint32_t)(r0i * TSTRIDE + seg * 16);
    const uint32_t so1 = (uint32_t)(r1i * TSTRIDE + seg * 16);

    // fragment mapping (identical to validated R4 layout)
    const int lane = t & 31, wid = t >> 5;
    const int mbase = (wid & 3) * 32, nbase = (wid >> 2) * 64;
    const int lt = lane >> 3, ll = lane & 7;
    const int dr = (lt & 1) * 8, dk = (lt >> 1) * 8;
    const int a_off = (mbase + dr + ll) * TSTRIDE + dk * 2;
    const int b_off = (nbase + dr + ll) * TSTRIDE + dk * 2;

    float acc[2][8][4];
    #pragma unroll
    for (int a = 0; a < 2; a++)
        #pragma unroll
        for (int b = 0; b < 8; b++)
            #pragma unroll
            for (int c = 0; c < 4; c++) acc[a][b][c] = 0.f;

    // issue chunk 0
    {
        const uint32_t st = sbase;
        cp16(st + so0,             agh0);  cp16(st + so1,             agh1);
        cp16(st + PL_SZ + so0,     agl0);  cp16(st + PL_SZ + so1,     agl1);
        cp16(st + 2*PL_SZ + so0,   bgh0);  cp16(st + 2*PL_SZ + so1,   bgh1);
        cp16(st + 3*PL_SZ + so0,   bgl0);  cp16(st + 3*PL_SZ + so1,   bgl1);
        CP_COMMIT();
    }

    #pragma unroll 1
    for (int ch = 0; ch < 16; ch++) {
        CP_WAIT(0);
        __syncthreads();
        if (ch < 15) {
            const int k0 = (ch + 1) * 32;
            const uint32_t st = sbase + ((ch + 1) & 1) * CH_SZ;
            cp16(st + so0,           agh0 + k0);  cp16(st + so1,           agh1 + k0);
            cp16(st + PL_SZ + so0,   agl0 + k0);  cp16(st + PL_SZ + so1,   agl1 + k0);
            cp16(st + 2*PL_SZ + so0, bgh0 + k0);  cp16(st + 2*PL_SZ + so1, bgh1 + k0);
            cp16(st + 3*PL_SZ + so0, bgl0 + k0);  cp16(st + 3*PL_SZ + so1, bgl1 + k0);
            CP_COMMIT();
        }
        const uint32_t bu  = sbase + (ch & 1) * CH_SZ;
        const uint32_t Ahi = bu, Alo = bu + PL_SZ, Bhi = bu + 2*PL_SZ, Blo = bu + 3*PL_SZ;
        #pragma unroll
        for (int ks = 0; ks < 2; ks++) {
            uint32_t ah[2][4], al[2][4];
            #pragma unroll
            for (int mf = 0; mf < 2; mf++) {
                LDSM_X4(ah[mf][0], ah[mf][1], ah[mf][2], ah[mf][3],
                        Ahi + a_off + mf * 1280 + ks * 32);
                LDSM_X4(al[mf][0], al[mf][1], al[mf][2], al[mf][3],
                        Alo + a_off + mf * 1280 + ks * 32);
            }
            #pragma unroll
            for (int j = 0; j < 4; j++) {
                uint32_t bh[4], bl[4];
                LDSM_X4(bh[0], bh[1], bh[2], bh[3], Bhi + b_off + j * 1280 + ks * 32);
                LDSM_X4(bl[0], bl[1], bl[2], bl[3], Blo + b_off + j * 1280 + ks * 32);
                #pragma unroll
                for (int mf = 0; mf < 2; mf++) {
                    mma_bf16(acc[mf][2*j],   ah[mf], bh[0], bh[2]);
                    mma_bf16(acc[mf][2*j],   ah[mf], bl[0], bl[2]);
                    mma_bf16(acc[mf][2*j],   al[mf], bh[0], bh[2]);
                    mma_bf16(acc[mf][2*j+1], ah[mf], bh[1], bh[3]);
                    mma_bf16(acc[mf][2*j+1], ah[mf], bl[1], bl[3]);
                    mma_bf16(acc[mf][2*j+1], al[mf], bh[1], bh[3]);
                }
            }
        }
    }

    const int g = lane >> 2, tg = (lane & 3) * 2;
    #pragma unroll
    for (int mf = 0; mf < 2; mf++) {
        #pragma unroll
        for (int jj = 0; jj < 8; jj++) {
            const int nloc = nbase + jj * 8 + tg;
            const float b0 = bsum[nloc], b1 = bsum[nloc + 1];
            const int r0 = m0 + mbase + mf * 16 + g;
            const size_t col = (size_t)(n0 + nloc);
            *(float2*)(C + (size_t)r0 * G4 + col) =
                make_float2(acc[mf][jj][0] + b0, acc[mf][jj][1] + b1);
            *(float2*)(C + (size_t)(r0 + 8) * G4 + col) =
                make_float2(acc[mf][jj][2] + b0, acc[mf][jj][3] + b1);
        }
    }
}

// ---------------- small fp32 GEMM (hTW only) --------------------------------------
__global__ void sgemm64(const float* __restrict__ A, const int* __restrict__ gather,
                        const float* __restrict__ W, int M, int N, int K,
                        const float* __restrict__ bias1, const float* __restrict__ bias2,
                        float* __restrict__ C)
{
    __shared__ __align__(16) float As[16][68];
    __shared__ __align__(16) float Bs[16][64];
    const int t  = threadIdx.x;
    const int m0 = blockIdx.y * 64;
    const int n0 = blockIdx.x * 64;
    const int c0 = 4 * (t & 15);
    const int r0 = 4 * (t >> 4);
    const int mload = t >> 2;
    const int kq    = (t & 3) * 4;
    const int nload = t & 63;
    const int kload = t >> 6;

    const float* arow;
    {
        int mg = m0 + mload;
        arow = gather ? (A + (size_t)gather[mg] * K) : (A + (size_t)mg * K);
    }

    float acc[4][4] = {};
    for (int k0 = 0; k0 < K; k0 += 16) {
        float4 a4 = *(const float4*)(arow + k0 + kq);
        As[kq + 0][mload] = a4.x; As[kq + 1][mload] = a4.y;
        As[kq + 2][mload] = a4.z; As[kq + 3][mload] = a4.w;
        #pragma unroll
        for (int p = 0; p < 4; p++) {
            int kk = kload + p * 4;
            Bs[kk][nload] = W[(size_t)(k0 + kk) * N + n0 + nload];
        }
        __syncthreads();
        #pragma unroll
        for (int kk = 0; kk < 16; kk++) {
            float4 a = *(const float4*)&As[kk][r0];
            float4 b = *(const float4*)&Bs[kk][c0];
            acc[0][0] += a.x*b.x; acc[0][1] += a.x*b.y; acc[0][2] += a.x*b.z; acc[0][3] += a.x*b.w;
            acc[1][0] += a.y*b.x; acc[1][1] += a.y*b.y; acc[1][2] += a.y*b.z; acc[1][3] += a.y*b.w;
            acc[2][0] += a.z*b.x; acc[2][1] += a.z*b.y; acc[2][2] += a.z*b.z; acc[2][3] += a.z*b.w;
            acc[3][0] += a.w*b.x; acc[3][1] += a.w*b.y; acc[3][2] += a.w*b.z; acc[3][3] += a.w*b.w;
        }
        __syncthreads();
    }
    float badd[4];
    #pragma unroll
    for (int j = 0; j < 4; j++) {
        float b = 0.f;
        if (bias1) b += bias1[n0 + c0 + j];
        if (bias2) b += bias2[n0 + c0 + j];
        badd[j] = b;
    }
    #pragma unroll
    for (int i = 0; i < 4; i++) {
        float4 v = make_float4(acc[i][0] + badd[0], acc[i][1] + badd[1],
                               acc[i][2] + badd[2], acc[i][3] + badd[3]);
        *(float4*)&C[(size_t)(m0 + r0 + i) * N + n0 + c0] = v;
    }
}

// ---------------- persistent forward LSTM scan (tensor-core, cp.async staged) ----
// 6 chunks of 64 rows x 128 k, 3-stage cp.async pipeline, split grid barrier.
#define WSTRIDE 1552
#define HSTRIDE 272
#define HPL     17408                // 64 rows x 272
#define HST_SZ  (2 * HPL)            // hi + lo per stage = 34816
#define FW_WH_HI 0
#define FW_WH_LO 49664
#define FW_HID   99328               // 3 stages x 34816 = 104448
#define FW_GS    203776              // 32 cols x 68 fp32 = 8704
#define FW_SMEM  212480

__global__ void __launch_bounds__(256, 1) fwd_lstm_mma(
    const float* __restrict__ Wh,    // [768][3072]
    const float* __restrict__ xf,    // [S*B][3072]
    float* __restrict__ hsf)         // [S*B][768]
{
    extern __shared__ char sm[];
    const uint32_t sbase = smem_u32(sm);
    float* gs = (float*)(sm + FW_GS);
    const int t  = threadIdx.x;
    const int bx = blockIdx.x;
    const int j0 = bx * 8;

    const unsigned gen0 = g_gen2;    // barrier epoch base (before any arrive)

    // stage Wh slice as bf16 hi/lo, n-major [32][768]
    for (int idx = t; idx < 768 * 32; idx += 256) {
        int n = idx & 31, k = idx >> 5;
        float v = Wh[(size_t)k * 3072 + (n >> 3) * 768 + j0 + (n & 7)];
        uint32_t b = __float_as_uint(v);
        *(uint16_t*)(sm + FW_WH_HI + n * WSTRIDE + k * 2) = (uint16_t)(b >> 16);
        *(uint16_t*)(sm + FW_WH_LO + n * WSTRIDE + k * 2) =
            bf16rn(v - __uint_as_float(b & 0xFFFF0000u));
    }

    const int lane = t & 31, wid = t >> 5;
    const int wm = wid & 3, wn = wid >> 2;
    const int lt = lane >> 3, ll = lane & 7;
    const int dr = (lt & 1) * 8, dk16 = (lt >> 1) * 16;
    const uint32_t a_off = (uint32_t)((wm * 16 + dr + ll) * HSTRIDE + dk16);
    const uint32_t b_hiA = sbase + FW_WH_HI + (wn * 16 + dr + ll) * WSTRIDE + dk16;
    const uint32_t b_loA = sbase + FW_WH_LO + (wn * 16 + dr + ll) * WSTRIDE + dk16;

    // hid staging map: 4 x 16B per plane per thread (full 256B rows)
    const int srow = t >> 2, sseg = t & 3;
    const uint32_t s_off = (uint32_t)(srow * HSTRIDE + sseg * 16);
    const int g_off = srow * 768 + sseg * 8;   // + ch*128, elements; +32 per segment

    // epilogue mapping
    const int h_a = t & 7, row_a = t >> 3;
    const int h_b = h_a,   row_b = 32 + (t >> 3);
    float creg_a = 0.f, creg_b = 0.f;

    // prefetch xf for step 0
    float xfa[4], xfb[4];
    {
        size_t ba = ((size_t)row_a) * 3072 + j0 + h_a;
        size_t bb = ((size_t)row_b) * 3072 + j0 + h_b;
        #pragma unroll
        for (int g = 0; g < 4; g++) { xfa[g] = xf[ba + g * 768]; xfb[g] = xf[bb + g * 768]; }
    }
    __syncthreads();

    for (int s = 0; s < SS; s++) {
        float acc[2][4] = {};
        if (s > 0) {
            bar_wait(gen0 + (unsigned)s);
            const uint16_t* chi = g_hid_hi[s & 1];
            const uint16_t* clo = g_hid_lo[s & 1];
            // prologue: stage chunks 0, 1
            #pragma unroll
            for (int p = 0; p < 2; p++) {
                const uint32_t st = sbase + FW_HID + p * HST_SZ;
                const int go = g_off + p * 128;
                #pragma unroll
                for (int j = 0; j < 4; j++) {
                    cp16(st + s_off + j * 64,       chi + go + j * 32);
                    cp16(st + HPL + s_off + j * 64, clo + go + j * 32);
                }
                CP_COMMIT();
            }
            #pragma unroll 1
            for (int ch = 0; ch < 6; ch++) {
                if (ch < 5) { CP_WAIT(1); } else { CP_WAIT(0); }
                __syncthreads();
                if (ch < 4) {
                    const int nc = ch + 2;
                    const uint32_t st = sbase + FW_HID + (nc % 3) * HST_SZ;
                    const int go = g_off + nc * 128;
                    #pragma unroll
                    for (int j = 0; j < 4; j++) {
                        cp16(st + s_off + j * 64,       chi + go + j * 32);
                        cp16(st + HPL + s_off + j * 64, clo + go + j * 32);
                    }
                    CP_COMMIT();
                }
                const uint32_t Ah  = sbase + FW_HID + (ch % 3) * HST_SZ + a_off;
                const uint32_t Al  = Ah + HPL;
                const uint32_t wko = (uint32_t)ch * 256;
                #pragma unroll
                for (int kf = 0; kf < 8; kf++) {
                    uint32_t ah[4], al[4], bh[4], bl[4];
                    LDSM_X4(ah[0], ah[1], ah[2], ah[3], Ah + kf * 32);
                    LDSM_X4(al[0], al[1], al[2], al[3], Al + kf * 32);
                    LDSM_X4(bh[0], bh[1], bh[2], bh[3], b_hiA + wko + kf * 32);
                    LDSM_X4(bl[0], bl[1], bl[2], bl[3], b_loA + wko + kf * 32);
                    mma_bf16(acc[0], ah, bh[0], bh[2]);
                    mma_bf16(acc[0], ah, bl[0], bl[2]);
                    mma_bf16(acc[0], al, bh[0], bh[2]);
                    mma_bf16(acc[1], ah, bh[1], bh[3]);
                    mma_bf16(acc[1], ah, bl[1], bl[3]);
                    mma_bf16(acc[1], al, bh[1], bh[3]);
                }
            }
        }
        // stash gates
        {
            const int g = lane >> 2, tg = (lane & 3) * 2;
            #pragma unroll
            for (int nf = 0; nf < 2; nf++) {
                int col = wn * 16 + nf * 8 + tg;
                int row = wm * 16 + g;
                gs[col * 68 + row]           = acc[nf][0];
                gs[(col + 1) * 68 + row]     = acc[nf][1];
                gs[col * 68 + row + 8]       = acc[nf][2];
                gs[(col + 1) * 68 + row + 8] = acc[nf][3];
            }
        }
        __syncthreads();

        uint16_t* nhi = g_hid_hi[(s + 1) & 1];
        uint16_t* nlo = g_hid_lo[(s + 1) & 1];
        {
            float gr = gs[( 0 + h_a) * 68 + row_a] + xfa[0];
            float gf = gs[( 8 + h_a) * 68 + row_a] + xfa[1];
            float gg = gs[(16 + h_a) * 68 + row_a] + xfa[2];
            float go = gs[(24 + h_a) * 68 + row_a] + xfa[3];
            float c  = sigmoidf_(gf) * creg_a + sigmoidf_(gr) * tanhf(gg);
            creg_a = c;
            float hv = sigmoidf_(go) * tanhf(c);
            int gi = row_a * 768 + j0 + h_a;
            uint32_t b = __float_as_uint(hv);
            nhi[gi] = (uint16_t)(b >> 16);
            nlo[gi] = bf16rn(hv - __uint_as_float(b & 0xFFFF0000u));
            hsf[((size_t)s * 64 + row_a) * 768 + j0 + h_a] = hv;
        }
        {
            float gr = gs[( 0 + h_b) * 68 + row_b] + xfb[0];
            float gf = gs[( 8 + h_b) * 68 + row_b] + xfb[1];
            float gg = gs[(16 + h_b) * 68 + row_b] + xfb[2];
            float go = gs[(24 + h_b) * 68 + row_b] + xfb[3];
            float c  = sigmoidf_(gf) * creg_b + sigmoidf_(gr) * tanhf(gg);
            creg_b = c;
            float hv = sigmoidf_(go) * tanhf(c);
            int gi = row_b * 768 + j0 + h_b;
            uint32_t b = __float_as_uint(hv);
            nhi[gi] = (uint16_t)(b >> 16);
            nlo[gi] = bf16rn(hv - __uint_as_float(b & 0xFFFF0000u));
            hsf[((size_t)s * 64 + row_b) * 768 + j0 + h_b] = hv;
        }
        bar_arrive(bx);

        // prefetch xf for next step (overlaps other blocks' barrier arrival)
        if (s + 1 < SS) {
            size_t ba = ((size_t)(s + 1) * 64 + row_a) * 3072 + j0 + h_a;
            size_t bb = ((size_t)(s + 1) * 64 + row_b) * 3072 + j0 + h_b;
            #pragma unroll
            for (int g = 0; g < 4; g++) { xfa[g] = xf[ba + g * 768]; xfb[g] = xf[bb + g * 768]; }
        }
    }
}

// ---------------- backward direction (pipelined loads) ----------------------------
__global__ void bwd_scan(const float* __restrict__ xb, const float* __restrict__ hTW,
                         float* __restrict__ hsb)
{
    int tid = blockIdx.x * blockDim.x + threadIdx.x;
    int h = tid % 768, b = tid / 768;
    float hr = hTW[b * 3072 + h];
    float hf = hTW[b * 3072 + 768 + h];
    float hg = hTW[b * 3072 + 1536 + h];
    float ho = hTW[b * 3072 + 2304 + h];
    size_t base = ((size_t)511 * 64 + b) * 3072 + h;
    float a0 = xb[base], a1 = xb[base + 768], a2 = xb[base + 1536], a3 = xb[base + 2304];
    float c2 = 0.f;
    for (int s = SS - 1; s >= 0; s--) {
        float x0 = a0, x1 = a1, x2 = a2, x3 = a3;
        if (s > 0) {
            base -= (size_t)64 * 3072;
            a0 = xb[base]; a1 = xb[base + 768]; a2 = xb[base + 1536]; a3 = xb[base + 2304];
        }
        float r = sigmoidf_(x0 + hr), f = sigmoidf_(x1 + hf);
        float g = tanhf(x2 + hg),     o = sigmoidf_(x3 + ho);
        c2 = f * c2 + r * g;
        hsb[((size_t)s * 64 + b) * 768 + h] = o * tanhf(c2);
    }
}

// ---------------- output GEMM -----------------------------------------------------
__global__ void out_gemm(const float* __restrict__ hsf, const float* __restrict__ hsb,
                         const float* __restrict__ Wout, const float* __restrict__ bout,
                         const int* __restrict__ tokens, float* __restrict__ out)
{
    __shared__ __align__(16) float As[16][132];
    __shared__ __align__(16) float Bs[16][32];
    const int t  = threadIdx.x;
    const int m0 = blockIdx.y * 128;
    const int c0 = 4 * (t & 7);
    const int r0 = 4 * (t >> 3);
    const int mload = t >> 2;
    const int kq    = (t & 3) * 4;
    float acc[4][4] = {};
    for (int k0 = 0; k0 < 1536; k0 += 16) {
        const float* srcbase = (k0 < 768) ? hsf : hsb;
        int koff = (k0 < 768) ? k0 : (k0 - 768);
        #pragma unroll
        for (int half = 0; half < 2; half++) {
            int m = mload + half * 64;
            float4 v = *(const float4*)(srcbase + (size_t)(m0 + m) * 768 + koff + kq);
            As[kq + 0][m] = v.x; As[kq + 1][m] = v.y;
            As[kq + 2][m] = v.z; As[kq + 3][m] = v.w;
        }
        #pragma unroll
        for (int p = 0; p < 2; p++) {
            int idx = t + p * 256;
            int kk = idx >> 5, n = idx & 31;
            Bs[kk][n] = Wout[(size_t)(k0 + kk) * 32 + n];
        }
        __syncthreads();
        #pragma unroll
        for (int kk = 0; kk < 16; kk++) {
            float4 a = *(const float4*)&As[kk][r0];
            float4 b = *(const float4*)&Bs[kk][c0];
            acc[0][0] += a.x*b.x; acc[0][1] += a.x*b.y; acc[0][2] += a.x*b.z; acc[0][3] += a.x*b.w;
            acc[1][0] += a.y*b.x; acc[1][1] += a.y*b.y; acc[1][2] += a.y*b.z; acc[1][3] += a.y*b.w;
            acc[2][0] += a.z*b.x; acc[2][1] += a.z*b.y; acc[2][2] += a.z*b.z; acc[2][3] += a.z*b.w;
            acc[3][0] += a.w*b.x; acc[3][1] += a.w*b.y; acc[3][2] += a.w*b.z; acc[3][3] += a.w*b.w;
        }
        __syncthreads();
    }
    #pragma unroll
    for (int i = 0; i < 4; i++) {
        int m = m0 + r0 + i;
        float4 v = make_float4(acc[i][0] + bout[c0],     acc[i][1] + bout[c0 + 1],
                               acc[i][2] + bout[c0 + 2], acc[i][3] + bout[c0 + 3]);
        if (c0 == 0 && tokens[m] == 1) v.x += 10000.0f;
        *(float4*)&out[(size_t)m * 32 + c0] = v;
    }
}

// ---------------- launch ----------------------------------------------------------
extern "C" void kernel_launch(void* const* d_in, const int* in_sizes, int n_in,
                              void* d_out, int out_size)
{
    const int*   tokens    = (const int*)  d_in[0];
    const float* embedding = (const float*)d_in[2];
    const float* Wi_f      = (const float*)d_in[3];
    const float* bi_f      = (const float*)d_in[4];
    const float* Wh_f      = (const float*)d_in[5];
    const float* bh_f      = (const float*)d_in[6];
    const float* Wi_b      = (const float*)d_in[7];
    const float* bi_b      = (const float*)d_in[8];
    const float* Wh_b      = (const float*)d_in[9];
    const float* bh_b      = (const float*)d_in[10];
    const float* Wout      = (const float*)d_in[11];
    const float* bout      = (const float*)d_in[12];
    float* out = (float*)d_out;

    float *xf, *xb, *hsf, *hsb, *hTW;
    uint16_t *ehi, *elo, *wthi, *wtlo;
    cudaGetSymbolAddress((void**)&xf,  g_xf);
    cudaGetSymbolAddress((void**)&xb,  g_xb);
    cudaGetSymbolAddress((void**)&hsf, g_hsf);
    cudaGetSymbolAddress((void**)&hsb, g_hsb);
    cudaGetSymbolAddress((void**)&hTW, g_hTW);
    cudaGetSymbolAddress((void**)&ehi, g_emb_hi);
    cudaGetSymbolAddress((void**)&elo, g_emb_lo);
    cudaGetSymbolAddress((void**)&wthi, g_wt_hi);
    cudaGetSymbolAddress((void**)&wtlo, g_wt_lo);

    cudaFuncSetAttribute(fwd_lstm_mma, cudaFuncAttributeMaxDynamicSharedMemorySize, FW_SMEM);
    cudaFuncSetAttribute(mma_gemm, cudaFuncAttributeMaxDynamicSharedMemorySize, GEMM_SMEM);

    // 0: pre-convert embedding + Wi matrices to bf16 hi/lo planes
    conv_emb<<<(VV * EE / 4 + 255) / 256, 256>>>((const float4*)embedding,
                                                 (uint2*)ehi, (uint2*)elo, VV * EE / 4);
    conv_wt<<<dim3(G4 / 32, EE / 32), dim3(32, 8)>>>(Wi_f, wthi,            wtlo);
    conv_wt<<<dim3(G4 / 32, EE / 32), dim3(32, 8)>>>(Wi_b, wthi + G4 * EE,  wtlo + G4 * EE);

    // 1+2: input gate precompute on tensor cores (bf16x3, cp.async staged)
    dim3 gG(G4 / 128, SB / 128);
    mma_gemm<<<gG, 256, GEMM_SMEM>>>(tokens, wthi,           wtlo,           bi_f, bh_f, xf);
    mma_gemm<<<gG, 256, GEMM_SMEM>>>(tokens, wthi + G4 * EE, wtlo + G4 * EE, nullptr, nullptr, xb);

    // 3: forward recurrence (persistent, tensor-core)
    fwd_lstm_mma<<<NBLK_FWD, 256, FW_SMEM>>>(Wh_f, xf, hsf);

    // 4: hTW = hT @ Wh_b + bi_b + bh_b
    sgemm64<<<dim3(G4 / 64, 1), 256>>>(hsf + (size_t)(SS - 1) * BB * HH, nullptr, Wh_b,
                                       BB, G4, HH, bi_b, bh_b, hTW);

    // 5: backward direction
    bwd_scan<<<(BB * HH) / 256, 256>>>(xb, hTW, hsb);

    // 6: output projection + pad bias
    out_gemm<<<dim3(1, SB / 128), 256>>>(hsf, hsb, Wout, bout, tokens, out);
}

// round 13
// speedup vs baseline: 1.0559x; 1.0043x over previous
#include <cuda_runtime.h>
#include <cuda_bf16.h>
#include <math.h>
#include <stdint.h>

#define SS   512
#define BB   64
#define EE   512
#define HH   768
#define G4   3072      // 4*H
#define SB   (SS*BB)   // 32768
#define VV   32000
#define NBLK_FWD 96

// ---------------- scratch (static device globals; allocation-free launch) --------
__device__ float g_xf [SB * G4];
__device__ float g_xb [SB * G4];
__device__ float g_hsf[SB * HH];
__device__ float g_hsb[SB * HH];
__device__ float g_hTW[BB * G4];
__device__ uint16_t g_hid_hi[2][BB * HH];
__device__ uint16_t g_hid_lo[2][BB * HH];
__device__ uint16_t g_emb_hi[VV * EE];      // bf16 hi plane of embedding
__device__ uint16_t g_emb_lo[VV * EE];      // bf16 lo (residual) plane
__device__ uint16_t g_wt_hi[2][G4 * EE];    // Wi_f / Wi_b transposed n-major planes
__device__ uint16_t g_wt_lo[2][G4 * EE];
// two-level barrier state
__device__ unsigned g_cnt_sub[6 * 32];      // one counter per 128B line
__device__ unsigned g_cnt_top;
__device__ volatile unsigned g_gen2;

// accurate transcendentals (libm; validated at rel_err 8.3e-8 in R4)
__device__ __forceinline__ float sigmoidf_(float x) { return 1.0f / (1.0f + expf(-x)); }

__device__ __forceinline__ uint32_t smem_u32(const void* p) {
    uint32_t a;
    asm("{ .reg .u64 t; cvta.to.shared.u64 t, %1; cvt.u32.u64 %0, t; }" : "=r"(a) : "l"(p));
    return a;
}
__device__ __forceinline__ uint32_t bpack(float e0, float e1) {
    uint32_t r;
    asm("cvt.rn.bf16x2.f32 %0, %1, %2;" : "=r"(r) : "f"(e1), "f"(e0));
    return r;
}
__device__ __forceinline__ uint16_t bf16rn(float x) {
    __nv_bfloat16 h = __float2bfloat16(x);
    return *(uint16_t*)&h;
}

#define LDSM_X4(r0, r1, r2, r3, addr)                                           \
    asm volatile("ldmatrix.sync.aligned.m8n8.x4.shared.b16 {%0,%1,%2,%3}, [%4];" \
                 : "=r"(r0), "=r"(r1), "=r"(r2), "=r"(r3) : "r"(addr))

__device__ __forceinline__ void mma_bf16(float (&d)[4], const uint32_t (&a)[4],
                                         uint32_t b0, uint32_t b1) {
    asm volatile("mma.sync.aligned.m16n8k16.row.col.f32.bf16.bf16.f32 "
                 "{%0,%1,%2,%3}, {%4,%5,%6,%7}, {%8,%9}, {%0,%1,%2,%3};"
                 : "+f"(d[0]), "+f"(d[1]), "+f"(d[2]), "+f"(d[3])
                 : "r"(a[0]), "r"(a[1]), "r"(a[2]), "r"(a[3]), "r"(b0), "r"(b1));
}

// ---------------- cp.async helpers ------------------------------------------------
__device__ __forceinline__ void cp16(uint32_t dst, const void* src) {
    asm volatile("cp.async.cg.shared.global [%0], [%1], 16;\n" :: "r"(dst), "l"(src));
}
#define CP_COMMIT() asm volatile("cp.async.commit_group;\n" ::: "memory")
#define CP_WAIT(n)  asm volatile("cp.async.wait_group %0;\n" :: "n"(n) : "memory")

// ---------------- split two-level grid barrier ------------------------------------
__device__ __forceinline__ void bar_arrive(int bx) {
    __syncthreads();
    __threadfence();
    if (threadIdx.x == 0) {
        int grp = bx >> 4;                      // 6 groups of 16
        if (atomicAdd(&g_cnt_sub[grp * 32], 1u) == 15u) {
            if (atomicAdd(&g_cnt_top, 1u) == 5u) {
                #pragma unroll
                for (int i = 0; i < 6; i++) g_cnt_sub[i * 32] = 0u;
                g_cnt_top = 0u;
                __threadfence();
                g_gen2 = g_gen2 + 1u;
            }
        }
    }
}
__device__ __forceinline__ void bar_wait(unsigned target) {
    if (threadIdx.x == 0) {
        while (g_gen2 < target) { }
    }
    __syncthreads();
    __threadfence();
}

// =================== pre-conversion kernels =======================================
__global__ void conv_emb(const float4* __restrict__ E,
                         uint2* __restrict__ hi, uint2* __restrict__ lo, int n4)
{
    int i = blockIdx.x * 256 + threadIdx.x;
    if (i >= n4) return;
    float4 v = E[i];
    uint32_t bx = __float_as_uint(v.x), by = __float_as_uint(v.y);
    uint32_t bz = __float_as_uint(v.z), bw = __float_as_uint(v.w);
    hi[i] = make_uint2(__byte_perm(bx, by, 0x7632), __byte_perm(bz, bw, 0x7632));
    float lx = v.x - __uint_as_float(bx & 0xFFFF0000u);
    float ly = v.y - __uint_as_float(by & 0xFFFF0000u);
    float lz = v.z - __uint_as_float(bz & 0xFFFF0000u);
    float lw = v.w - __uint_as_float(bw & 0xFFFF0000u);
    lo[i] = make_uint2(bpack(lx, ly), bpack(lz, lw));
}

// transpose W[512][3072] -> planes [3072][512]
__global__ void conv_wt(const float* __restrict__ W,
                        uint16_t* __restrict__ hi, uint16_t* __restrict__ lo)
{
    __shared__ float tile[32][33];
    int n0 = blockIdx.x * 32, k0 = blockIdx.y * 32;
    int tx = threadIdx.x, ty = threadIdx.y;   // (32, 8)
    #pragma unroll
    for (int j = 0; j < 4; j++)
        tile[ty + 8 * j][tx] = W[(size_t)(k0 + ty + 8 * j) * G4 + n0 + tx];
    __syncthreads();
    #pragma unroll
    for (int j = 0; j < 4; j++) {
        int n = ty + 8 * j;
        float v = tile[tx][n];                // = W[k0+tx][n0+n]
        uint32_t b = __float_as_uint(v);
        size_t o = (size_t)(n0 + n) * EE + k0 + tx;
        hi[o] = (uint16_t)(b >> 16);
        lo[o] = bf16rn(v - __uint_as_float(b & 0xFFFF0000u));
    }
}

// =================== bf16x3 mma.sync GEMM (pre-converted, cp.async staged) ========
// CTA 128x128, BK=32, 2-stage cp.async; planes: Ahi/Alo/Bhi/Blo, 128 rows x 80B.
#define TSTRIDE 80
#define PL_SZ  (128 * TSTRIDE)       // 10240
#define CH_SZ  (4 * PL_SZ)           // 40960
#define GEMM_SMEM (2 * CH_SZ + 512)  // 82432

__global__ void __launch_bounds__(256, 2) mma_gemm(
    const int* __restrict__ tokens,
    const uint16_t* __restrict__ Whi, const uint16_t* __restrict__ Wlo,
    const float* __restrict__ bias1, const float* __restrict__ bias2,
    float* __restrict__ C)
{
    extern __shared__ char sm[];
    const uint32_t sbase = smem_u32(sm);
    const int t  = threadIdx.x;
    const int n0 = blockIdx.x * 128;
    const int m0 = blockIdx.y * 128;
    float* bsum = (float*)(sm + 2 * CH_SZ);
    if (t < 128) bsum[t] = bias1 ? (bias1[n0 + t] + bias2[n0 + t]) : 0.f;

    // staging mapping: thread -> (row, 16B segment); 2 rows per thread per plane
    const int r0i = t >> 2, seg = t & 3;
    const int r1i = r0i + 64;
    const uint16_t* agh0 = g_emb_hi + (size_t)tokens[m0 + r0i] * EE + seg * 8;
    const uint16_t* agl0 = g_emb_lo + (size_t)tokens[m0 + r0i] * EE + seg * 8;
    const uint16_t* agh1 = g_emb_hi + (size_t)tokens[m0 + r1i] * EE + seg * 8;
    const uint16_t* agl1 = g_emb_lo + (size_t)tokens[m0 + r1i] * EE + seg * 8;
    const uint16_t* bgh0 = Whi + (size_t)(n0 + r0i) * EE + seg * 8;
    const uint16_t* bgl0 = Wlo + (size_t)(n0 + r0i) * EE + seg * 8;
    const uint16_t* bgh1 = Whi + (size_t)(n0 + r1i) * EE + seg * 8;
    const uint16_t* bgl1 = Wlo + (size_t)(n0 + r1i) * EE + seg * 8;
    const uint32_t so0 = (uint32_t)(r0i * TSTRIDE + seg * 16);
    const uint32_t so1 = (uint32_t)(r1i * TSTRIDE + seg * 16);

    // fragment mapping (identical to validated R4 layout)
    const int lane = t & 31, wid = t >> 5;
    const int mbase = (wid & 3) * 32, nbase = (wid >> 2) * 64;
    const int lt = lane >> 3, ll = lane & 7;
    const int dr = (lt & 1) * 8, dk = (lt >> 1) * 8;
    const int a_off = (mbase + dr + ll) * TSTRIDE + dk * 2;
    const int b_off = (nbase + dr + ll) * TSTRIDE + dk * 2;

    float acc[2][8][4];
    #pragma unroll
    for (int a = 0; a < 2; a++)
        #pragma unroll
        for (int b = 0; b < 8; b++)
            #pragma unroll
            for (int c = 0; c < 4; c++) acc[a][b][c] = 0.f;

    // issue chunk 0
    {
        const uint32_t st = sbase;
        cp16(st + so0,             agh0);  cp16(st + so1,             agh1);
        cp16(st + PL_SZ + so0,     agl0);  cp16(st + PL_SZ + so1,     agl1);
        cp16(st + 2*PL_SZ + so0,   bgh0);  cp16(st + 2*PL_SZ + so1,   bgh1);
        cp16(st + 3*PL_SZ + so0,   bgl0);  cp16(st + 3*PL_SZ + so1,   bgl1);
        CP_COMMIT();
    }

    #pragma unroll 1
    for (int ch = 0; ch < 16; ch++) {
        CP_WAIT(0);
        __syncthreads();
        if (ch < 15) {
            const int k0 = (ch + 1) * 32;
            const uint32_t st = sbase + ((ch + 1) & 1) * CH_SZ;
            cp16(st + so0,           agh0 + k0);  cp16(st + so1,           agh1 + k0);
            cp16(st + PL_SZ + so0,   agl0 + k0);  cp16(st + PL_SZ + so1,   agl1 + k0);
            cp16(st + 2*PL_SZ + so0, bgh0 + k0);  cp16(st + 2*PL_SZ + so1, bgh1 + k0);
            cp16(st + 3*PL_SZ + so0, bgl0 + k0);  cp16(st + 3*PL_SZ + so1, bgl1 + k0);
            CP_COMMIT();
        }
        const uint32_t bu  = sbase + (ch & 1) * CH_SZ;
        const uint32_t Ahi = bu, Alo = bu + PL_SZ, Bhi = bu + 2*PL_SZ, Blo = bu + 3*PL_SZ;
        #pragma unroll
        for (int ks = 0; ks < 2; ks++) {
            uint32_t ah[2][4], al[2][4];
            #pragma unroll
            for (int mf = 0; mf < 2; mf++) {
                LDSM_X4(ah[mf][0], ah[mf][1], ah[mf][2], ah[mf][3],
                        Ahi + a_off + mf * 1280 + ks * 32);
                LDSM_X4(al[mf][0], al[mf][1], al[mf][2], al[mf][3],
                        Alo + a_off + mf * 1280 + ks * 32);
            }
            #pragma unroll
            for (int j = 0; j < 4; j++) {
                uint32_t bh[4], bl[4];
                LDSM_X4(bh[0], bh[1], bh[2], bh[3], Bhi + b_off + j * 1280 + ks * 32);
                LDSM_X4(bl[0], bl[1], bl[2], bl[3], Blo + b_off + j * 1280 + ks * 32);
                #pragma unroll
                for (int mf = 0; mf < 2; mf++) {
                    mma_bf16(acc[mf][2*j],   ah[mf], bh[0], bh[2]);
                    mma_bf16(acc[mf][2*j],   ah[mf], bl[0], bl[2]);
                    mma_bf16(acc[mf][2*j],   al[mf], bh[0], bh[2]);
                    mma_bf16(acc[mf][2*j+1], ah[mf], bh[1], bh[3]);
                    mma_bf16(acc[mf][2*j+1], ah[mf], bl[1], bl[3]);
                    mma_bf16(acc[mf][2*j+1], al[mf], bh[1], bh[3]);
                }
            }
        }
    }

    const int g = lane >> 2, tg = (lane & 3) * 2;
    #pragma unroll
    for (int mf = 0; mf < 2; mf++) {
        #pragma unroll
        for (int jj = 0; jj < 8; jj++) {
            const int nloc = nbase + jj * 8 + tg;
            const float b0 = bsum[nloc], b1 = bsum[nloc + 1];
            const int r0 = m0 + mbase + mf * 16 + g;
            const size_t col = (size_t)(n0 + nloc);
            *(float2*)(C + (size_t)r0 * G4 + col) =
                make_float2(acc[mf][jj][0] + b0, acc[mf][jj][1] + b1);
            *(float2*)(C + (size_t)(r0 + 8) * G4 + col) =
                make_float2(acc[mf][jj][2] + b0, acc[mf][jj][3] + b1);
        }
    }
}

// ---------------- small fp32 GEMM (hTW only) --------------------------------------
__global__ void sgemm64(const float* __restrict__ A, const int* __restrict__ gather,
                        const float* __restrict__ W, int M, int N, int K,
                        const float* __restrict__ bias1, const float* __restrict__ bias2,
                        float* __restrict__ C)
{
    __shared__ __align__(16) float As[16][68];
    __shared__ __align__(16) float Bs[16][64];
    const int t  = threadIdx.x;
    const int m0 = blockIdx.y * 64;
    const int n0 = blockIdx.x * 64;
    const int c0 = 4 * (t & 15);
    const int r0 = 4 * (t >> 4);
    const int mload = t >> 2;
    const int kq    = (t & 3) * 4;
    const int nload = t & 63;
    const int kload = t >> 6;

    const float* arow;
    {
        int mg = m0 + mload;
        arow = gather ? (A + (size_t)gather[mg] * K) : (A + (size_t)mg * K);
    }

    float acc[4][4] = {};
    for (int k0 = 0; k0 < K; k0 += 16) {
        float4 a4 = *(const float4*)(arow + k0 + kq);
        As[kq + 0][mload] = a4.x; As[kq + 1][mload] = a4.y;
        As[kq + 2][mload] = a4.z; As[kq + 3][mload] = a4.w;
        #pragma unroll
        for (int p = 0; p < 4; p++) {
            int kk = kload + p * 4;
            Bs[kk][nload] = W[(size_t)(k0 + kk) * N + n0 + nload];
        }
        __syncthreads();
        #pragma unroll
        for (int kk = 0; kk < 16; kk++) {
            float4 a = *(const float4*)&As[kk][r0];
            float4 b = *(const float4*)&Bs[kk][c0];
            acc[0][0] += a.x*b.x; acc[0][1] += a.x*b.y; acc[0][2] += a.x*b.z; acc[0][3] += a.x*b.w;
            acc[1][0] += a.y*b.x; acc[1][1] += a.y*b.y; acc[1][2] += a.y*b.z; acc[1][3] += a.y*b.w;
            acc[2][0] += a.z*b.x; acc[2][1] += a.z*b.y; acc[2][2] += a.z*b.z; acc[2][3] += a.z*b.w;
            acc[3][0] += a.w*b.x; acc[3][1] += a.w*b.y; acc[3][2] += a.w*b.z; acc[3][3] += a.w*b.w;
        }
        __syncthreads();
    }
    float badd[4];
    #pragma unroll
    for (int j = 0; j < 4; j++) {
        float b = 0.f;
        if (bias1) b += bias1[n0 + c0 + j];
        if (bias2) b += bias2[n0 + c0 + j];
        badd[j] = b;
    }
    #pragma unroll
    for (int i = 0; i < 4; i++) {
        float4 v = make_float4(acc[i][0] + badd[0], acc[i][1] + badd[1],
                               acc[i][2] + badd[2], acc[i][3] + badd[3]);
        *(float4*)&C[(size_t)(m0 + r0 + i) * N + n0 + c0] = v;
    }
}

// ---------------- persistent forward LSTM scan (tensor-core, cp.async staged) ----
// 6 chunks of 64 rows x 128 k, 3-stage cp.async pipeline, split grid barrier.
#define WSTRIDE 1552
#define HSTRIDE 272
#define HPL     17408                // 64 rows x 272
#define HST_SZ  (2 * HPL)            // hi + lo per stage = 34816
#define FW_WH_HI 0
#define FW_WH_LO 49664
#define FW_HID   99328               // 3 stages x 34816 = 104448
#define FW_GS    203776              // 32 cols x 68 fp32 = 8704
#define FW_SMEM  212480

__global__ void __launch_bounds__(256, 1) fwd_lstm_mma(
    const float* __restrict__ Wh,    // [768][3072]
    const float* __restrict__ xf,    // [S*B][3072]
    float* __restrict__ hsf)         // [S*B][768]
{
    extern __shared__ char sm[];
    const uint32_t sbase = smem_u32(sm);
    float* gs = (float*)(sm + FW_GS);
    const int t  = threadIdx.x;
    const int bx = blockIdx.x;
    const int j0 = bx * 8;

    const unsigned gen0 = g_gen2;    // barrier epoch base (before any arrive)

    // stage Wh slice as bf16 hi/lo, n-major [32][768]
    for (int idx = t; idx < 768 * 32; idx += 256) {
        int n = idx & 31, k = idx >> 5;
        float v = Wh[(size_t)k * 3072 + (n >> 3) * 768 + j0 + (n & 7)];
        uint32_t b = __float_as_uint(v);
        *(uint16_t*)(sm + FW_WH_HI + n * WSTRIDE + k * 2) = (uint16_t)(b >> 16);
        *(uint16_t*)(sm + FW_WH_LO + n * WSTRIDE + k * 2) =
            bf16rn(v - __uint_as_float(b & 0xFFFF0000u));
    }

    const int lane = t & 31, wid = t >> 5;
    const int wm = wid & 3, wn = wid >> 2;
    const int lt = lane >> 3, ll = lane & 7;
    const int dr = (lt & 1) * 8, dk16 = (lt >> 1) * 16;
    const uint32_t a_off = (uint32_t)((wm * 16 + dr + ll) * HSTRIDE + dk16);
    const uint32_t b_hiA = sbase + FW_WH_HI + (wn * 16 + dr + ll) * WSTRIDE + dk16;
    const uint32_t b_loA = sbase + FW_WH_LO + (wn * 16 + dr + ll) * WSTRIDE + dk16;

    // hid staging map: 4 x 16B per plane per thread (full 256B rows)
    const int srow = t >> 2, sseg = t & 3;
    const uint32_t s_off = (uint32_t)(srow * HSTRIDE + sseg * 16);
    const int g_off = srow * 768 + sseg * 8;   // + ch*128, elements; +32 per segment

    // epilogue mapping
    const int h_a = t & 7, row_a = t >> 3;
    const int h_b = h_a,   row_b = 32 + (t >> 3);
    float creg_a = 0.f, creg_b = 0.f;

    // prefetch xf for step 0
    float xfa[4], xfb[4];
    {
        size_t ba = ((size_t)row_a) * 3072 + j0 + h_a;
        size_t bb = ((size_t)row_b) * 3072 + j0 + h_b;
        #pragma unroll
        for (int g = 0; g < 4; g++) { xfa[g] = xf[ba + g * 768]; xfb[g] = xf[bb + g * 768]; }
    }
    __syncthreads();

    for (int s = 0; s < SS; s++) {
        float acc[2][4] = {};
        if (s > 0) {
            bar_wait(gen0 + (unsigned)s);
            const uint16_t* chi = g_hid_hi[s & 1];
            const uint16_t* clo = g_hid_lo[s & 1];
            // prologue: stage chunks 0, 1
            #pragma unroll
            for (int p = 0; p < 2; p++) {
                const uint32_t st = sbase + FW_HID + p * HST_SZ;
                const int go = g_off + p * 128;
                #pragma unroll
                for (int j = 0; j < 4; j++) {
                    cp16(st + s_off + j * 64,       chi + go + j * 32);
                    cp16(st + HPL + s_off + j * 64, clo + go + j * 32);
                }
                CP_COMMIT();
            }
            #pragma unroll 1
            for (int ch = 0; ch < 6; ch++) {
                if (ch < 5) { CP_WAIT(1); } else { CP_WAIT(0); }
                __syncthreads();
                if (ch < 4) {
                    const int nc = ch + 2;
                    const uint32_t st = sbase + FW_HID + (nc % 3) * HST_SZ;
                    const int go = g_off + nc * 128;
                    #pragma unroll
                    for (int j = 0; j < 4; j++) {
                        cp16(st + s_off + j * 64,       chi + go + j * 32);
                        cp16(st + HPL + s_off + j * 64, clo + go + j * 32);
                    }
                    CP_COMMIT();
                }
                const uint32_t Ah  = sbase + FW_HID + (ch % 3) * HST_SZ + a_off;
                const uint32_t Al  = Ah + HPL;
                const uint32_t wko = (uint32_t)ch * 256;
                #pragma unroll
                for (int kf = 0; kf < 8; kf++) {
                    uint32_t ah[4], al[4], bh[4], bl[4];
                    LDSM_X4(ah[0], ah[1], ah[2], ah[3], Ah + kf * 32);
                    LDSM_X4(al[0], al[1], al[2], al[3], Al + kf * 32);
                    LDSM_X4(bh[0], bh[1], bh[2], bh[3], b_hiA + wko + kf * 32);
                    LDSM_X4(bl[0], bl[1], bl[2], bl[3], b_loA + wko + kf * 32);
                    mma_bf16(acc[0], ah, bh[0], bh[2]);
                    mma_bf16(acc[0], ah, bl[0], bl[2]);
                    mma_bf16(acc[0], al, bh[0], bh[2]);
                    mma_bf16(acc[1], ah, bh[1], bh[3]);
                    mma_bf16(acc[1], ah, bl[1], bl[3]);
                    mma_bf16(acc[1], al, bh[1], bh[3]);
                }
            }
        }
        // stash gates
        {
            const int g = lane >> 2, tg = (lane & 3) * 2;
            #pragma unroll
            for (int nf = 0; nf < 2; nf++) {
                int col = wn * 16 + nf * 8 + tg;
                int row = wm * 16 + g;
                gs[col * 68 + row]           = acc[nf][0];
                gs[(col + 1) * 68 + row]     = acc[nf][1];
                gs[col * 68 + row + 8]       = acc[nf][2];
                gs[(col + 1) * 68 + row + 8] = acc[nf][3];
            }
        }
        __syncthreads();

        uint16_t* nhi = g_hid_hi[(s + 1) & 1];
        uint16_t* nlo = g_hid_lo[(s + 1) & 1];
        {
            float gr = gs[( 0 + h_a) * 68 + row_a] + xfa[0];
            float gf = gs[( 8 + h_a) * 68 + row_a] + xfa[1];
            float gg = gs[(16 + h_a) * 68 + row_a] + xfa[2];
            float go = gs[(24 + h_a) * 68 + row_a] + xfa[3];
            float c  = sigmoidf_(gf) * creg_a + sigmoidf_(gr) * tanhf(gg);
            creg_a = c;
            float hv = sigmoidf_(go) * tanhf(c);
            int gi = row_a * 768 + j0 + h_a;
            uint32_t b = __float_as_uint(hv);
            nhi[gi] = (uint16_t)(b >> 16);
            nlo[gi] = bf16rn(hv - __uint_as_float(b & 0xFFFF0000u));
            hsf[((size_t)s * 64 + row_a) * 768 + j0 + h_a] = hv;
        }
        {
            float gr = gs[( 0 + h_b) * 68 + row_b] + xfb[0];
            float gf = gs[( 8 + h_b) * 68 + row_b] + xfb[1];
            float gg = gs[(16 + h_b) * 68 + row_b] + xfb[2];
            float go = gs[(24 + h_b) * 68 + row_b] + xfb[3];
            float c  = sigmoidf_(gf) * creg_b + sigmoidf_(gr) * tanhf(gg);
            creg_b = c;
            float hv = sigmoidf_(go) * tanhf(c);
            int gi = row_b * 768 + j0 + h_b;
            uint32_t b = __float_as_uint(hv);
            nhi[gi] = (uint16_t)(b >> 16);
            nlo[gi] = bf16rn(hv - __uint_as_float(b & 0xFFFF0000u));
            hsf[((size_t)s * 64 + row_b) * 768 + j0 + h_b] = hv;
        }
        bar_arrive(bx);

        // prefetch xf for next step (overlaps other blocks' barrier arrival)
        if (s + 1 < SS) {
            size_t ba = ((size_t)(s + 1) * 64 + row_a) * 3072 + j0 + h_a;
            size_t bb = ((size_t)(s + 1) * 64 + row_b) * 3072 + j0 + h_b;
            #pragma unroll
            for (int g = 0; g < 4; g++) { xfa[g] = xf[ba + g * 768]; xfb[g] = xf[bb + g * 768]; }
        }
    }
}

// ---------------- backward direction (pipelined loads) ----------------------------
__global__ void bwd_scan(const float* __restrict__ xb, const float* __restrict__ hTW,
                         float* __restrict__ hsb)
{
    int tid = blockIdx.x * blockDim.x + threadIdx.x;
    int h = tid % 768, b = tid / 768;
    float hr = hTW[b * 3072 + h];
    float hf = hTW[b * 3072 + 768 + h];
    float hg = hTW[b * 3072 + 1536 + h];
    float ho = hTW[b * 3072 + 2304 + h];
    size_t base = ((size_t)511 * 64 + b) * 3072 + h;
    float a0 = xb[base], a1 = xb[base + 768], a2 = xb[base + 1536], a3 = xb[base + 2304];
    float c2 = 0.f;
    for (int s = SS - 1; s >= 0; s--) {
        float x0 = a0, x1 = a1, x2 = a2, x3 = a3;
        if (s > 0) {
            base -= (size_t)64 * 3072;
            a0 = xb[base]; a1 = xb[base + 768]; a2 = xb[base + 1536]; a3 = xb[base + 2304];
        }
        float r = sigmoidf_(x0 + hr), f = sigmoidf_(x1 + hf);
        float g = tanhf(x2 + hg),     o = sigmoidf_(x3 + ho);
        c2 = f * c2 + r * g;
        hsb[((size_t)s * 64 + b) * 768 + h] = o * tanhf(c2);
    }
}

// ---------------- output GEMM -----------------------------------------------------
__global__ void out_gemm(const float* __restrict__ hsf, const float* __restrict__ hsb,
                         const float* __restrict__ Wout, const float* __restrict__ bout,
                         const int* __restrict__ tokens, float* __restrict__ out)
{
    __shared__ __align__(16) float As[16][132];
    __shared__ __align__(16) float Bs[16][32];
    const int t  = threadIdx.x;
    const int m0 = blockIdx.y * 128;
    const int c0 = 4 * (t & 7);
    const int r0 = 4 * (t >> 3);
    const int mload = t >> 2;
    const int kq    = (t & 3) * 4;
    float acc[4][4] = {};
    for (int k0 = 0; k0 < 1536; k0 += 16) {
        const float* srcbase = (k0 < 768) ? hsf : hsb;
        int koff = (k0 < 768) ? k0 : (k0 - 768);
        #pragma unroll
        for (int half = 0; half < 2; half++) {
            int m = mload + half * 64;
            float4 v = *(const float4*)(srcbase + (size_t)(m0 + m) * 768 + koff + kq);
            As[kq + 0][m] = v.x; As[kq + 1][m] = v.y;
            As[kq + 2][m] = v.z; As[kq + 3][m] = v.w;
        }
        #pragma unroll
        for (int p = 0; p < 2; p++) {
            int idx = t + p * 256;
            int kk = idx >> 5, n = idx & 31;
            Bs[kk][n] = Wout[(size_t)(k0 + kk) * 32 + n];
        }
        __syncthreads();
        #pragma unroll
        for (int kk = 0; kk < 16; kk++) {
            float4 a = *(const float4*)&As[kk][r0];
            float4 b = *(const float4*)&Bs[kk][c0];
            acc[0][0] += a.x*b.x; acc[0][1] += a.x*b.y; acc[0][2] += a.x*b.z; acc[0][3] += a.x*b.w;
            acc[1][0] += a.y*b.x; acc[1][1] += a.y*b.y; acc[1][2] += a.y*b.z; acc[1][3] += a.y*b.w;
            acc[2][0] += a.z*b.x; acc[2][1] += a.z*b.y; acc[2][2] += a.z*b.z; acc[2][3] += a.z*b.w;
            acc[3][0] += a.w*b.x; acc[3][1] += a.w*b.y; acc[3][2] += a.w*b.z; acc[3][3] += a.w*b.w;
        }
        __syncthreads();
    }
    #pragma unroll
    for (int i = 0; i < 4; i++) {
        int m = m0 + r0 + i;
        float4 v = make_float4(acc[i][0] + bout[c0],     acc[i][1] + bout[c0 + 1],
                               acc[i][2] + bout[c0 + 2], acc[i][3] + bout[c0 + 3]);
        if (c0 == 0 && tokens[m] == 1) v.x += 10000.0f;
        *(float4*)&out[(size_t)m * 32 + c0] = v;
    }
}

// ---------------- launch ----------------------------------------------------------
extern "C" void kernel_launch(void* const* d_in, const int* in_sizes, int n_in,
                              void* d_out, int out_size)
{
    const int*   tokens    = (const int*)  d_in[0];
    const float* embedding = (const float*)d_in[2];
    const float* Wi_f      = (const float*)d_in[3];
    const float* bi_f      = (const float*)d_in[4];
    const float* Wh_f      = (const float*)d_in[5];
    const float* bh_f      = (const float*)d_in[6];
    const float* Wi_b      = (const float*)d_in[7];
    const float* bi_b      = (const float*)d_in[8];
    const float* Wh_b      = (const float*)d_in[9];
    const float* bh_b      = (const float*)d_in[10];
    const float* Wout      = (const float*)d_in[11];
    const float* bout      = (const float*)d_in[12];
    float* out = (float*)d_out;

    float *xf, *xb, *hsf, *hsb, *hTW;
    uint16_t *ehi, *elo, *wthi, *wtlo;
    cudaGetSymbolAddress((void**)&xf,  g_xf);
    cudaGetSymbolAddress((void**)&xb,  g_xb);
    cudaGetSymbolAddress((void**)&hsf, g_hsf);
    cudaGetSymbolAddress((void**)&hsb, g_hsb);
    cudaGetSymbolAddress((void**)&hTW, g_hTW);
    cudaGetSymbolAddress((void**)&ehi, g_emb_hi);
    cudaGetSymbolAddress((void**)&elo, g_emb_lo);
    cudaGetSymbolAddress((void**)&wthi, g_wt_hi);
    cudaGetSymbolAddress((void**)&wtlo, g_wt_lo);

    cudaFuncSetAttribute(fwd_lstm_mma, cudaFuncAttributeMaxDynamicSharedMemorySize, FW_SMEM);
    cudaFuncSetAttribute(mma_gemm, cudaFuncAttributeMaxDynamicSharedMemorySize, GEMM_SMEM);

    // 0: pre-convert embedding + Wi matrices to bf16 hi/lo planes
    conv_emb<<<(VV * EE / 4 + 255) / 256, 256>>>((const float4*)embedding,
                                                 (uint2*)ehi, (uint2*)elo, VV * EE / 4);
    conv_wt<<<dim3(G4 / 32, EE / 32), dim3(32, 8)>>>(Wi_f, wthi,            wtlo);
    conv_wt<<<dim3(G4 / 32, EE / 32), dim3(32, 8)>>>(Wi_b, wthi + G4 * EE,  wtlo + G4 * EE);

    // 1+2: input gate precompute on tensor cores (bf16x3, cp.async staged)
    dim3 gG(G4 / 128, SB / 128);
    mma_gemm<<<gG, 256, GEMM_SMEM>>>(tokens, wthi,           wtlo,           bi_f, bh_f, xf);
    mma_gemm<<<gG, 256, GEMM_SMEM>>>(tokens, wthi + G4 * EE, wtlo + G4 * EE, nullptr, nullptr, xb);

    // 3: forward recurrence (persistent, tensor-core)
    fwd_lstm_mma<<<NBLK_FWD, 256, FW_SMEM>>>(Wh_f, xf, hsf);

    // 4: hTW = hT @ Wh_b + bi_b + bh_b
    sgemm64<<<dim3(G4 / 64, 1), 256>>>(hsf + (size_t)(SS - 1) * BB * HH, nullptr, Wh_b,
                                       BB, G4, HH, bi_b, bh_b, hTW);

    // 5: backward direction
    bwd_scan<<<(BB * HH) / 256, 256>>>(xb, hTW, hsb);

    // 6: output projection + pad bias
    out_gemm<<<dim3(1, SB / 128), 256>>>(hsf, hsb, Wout, bout, tokens, out);
}